// round 1
// baseline (speedup 1.0000x reference)
#include <cuda_runtime.h>
#include <cstdint>
#include <math.h>

#define S_DIM 2048
#define A_DIM 64
#define P_DIM 128
#define B_SZ 256
#define T_STEPS 32
#define HS_DIM (S_DIM + A_DIM + P_DIM)   // 2240
#define PRED_ELEMS ((size_t)T_STEPS * B_SZ * S_DIM)

// ---------------- device scratch (static, no allocations) ----------------
__device__ float g_fcW [S_DIM * HS_DIM];     // rounded fc_W      [2048,2240]
__device__ float g_fc1e[S_DIM * S_DIM];      // folded fc1 halves [2048,2048]
__device__ float g_fc2 [S_DIM * S_DIM];      // rounded fc2_W
__device__ float g_WW  [4 * S_DIM * S_DIM];  // rounded W_W       [8192,2048]
__device__ float g_hs  [B_SZ * HS_DIM];      // A for fc GEMM (tf32-rounded)
__device__ float g_h   [B_SZ * S_DIM];       // hidden carry (tf32-rounded)
__device__ float g_c   [B_SZ * S_DIM];       // cell (fp32)
__device__ float g_x1  [B_SZ * S_DIM];
__device__ float g_x2  [B_SZ * S_DIM];
__device__ float g_cc  [B_SZ * 4 * S_DIM];

// ---------------- helpers ----------------
__device__ __forceinline__ float rna_tf32(float x) {
    uint32_t u;
    asm("cvt.rna.tf32.f32 %0, %1;" : "=r"(u) : "f"(x));
    return __uint_as_float(u);
}

__device__ __forceinline__ void cp_async16(void* sdst, const void* gsrc) {
    unsigned s = (unsigned)__cvta_generic_to_shared(sdst);
    asm volatile("cp.async.cg.shared.global [%0], [%1], 16;\n" :: "r"(s), "l"(gsrc));
}

__device__ __forceinline__ void mma_tf32(float c[4],
                                         uint32_t a0, uint32_t a1, uint32_t a2, uint32_t a3,
                                         uint32_t b0, uint32_t b1) {
    asm volatile(
        "mma.sync.aligned.m16n8k8.row.col.f32.tf32.tf32.f32 "
        "{%0,%1,%2,%3}, {%4,%5,%6,%7}, {%8,%9}, {%0,%1,%2,%3};\n"
        : "+f"(c[0]), "+f"(c[1]), "+f"(c[2]), "+f"(c[3])
        : "r"(a0), "r"(a1), "r"(a2), "r"(a3), "r"(b0), "r"(b1));
}

// ---------------- generic tf32 GEMM: out = relu(A @ B^T (+bias)) ----------------
// A: [M,K] row-major (tf32-rounded fp32 bits), B: [N,K] row-major (tf32-rounded)
// out1: rna_tf32(relu(acc)) ; out2 (optional): relu(acc) fp32
// Requires M%64==0, N%64==0, K%32==0.
__global__ __launch_bounds__(128) void gemm_tf32_kernel(
    const float* __restrict__ A, const float* __restrict__ Bm,
    float* __restrict__ out1, float* __restrict__ out2,
    const float* __restrict__ bias, int M, int N, int K)
{
    __shared__ float As[2][64][36];
    __shared__ float Bs[2][64][36];

    const int tid  = threadIdx.x;
    const int warp = tid >> 5;
    const int lane = tid & 31;
    const int wm = warp >> 1;          // 0..1
    const int wn = warp & 1;           // 0..1
    const int g  = lane >> 2;          // 0..7
    const int tg = lane & 3;           // 0..3

    const int mbase = blockIdx.y * 64;
    const int nbase = blockIdx.x * 64;

    const float* Ab = A  + (size_t)mbase * K;
    const float* Bb = Bm + (size_t)nbase * K;

    float acc[2][4][4];
#pragma unroll
    for (int i = 0; i < 2; i++)
#pragma unroll
        for (int j = 0; j < 4; j++)
#pragma unroll
            for (int e = 0; e < 4; e++) acc[i][j][e] = 0.f;

    auto load_tile = [&](int stage, int k0) {
#pragma unroll
        for (int j = 0; j < 4; j++) {
            int id  = tid + 128 * j;           // 0..511
            int row = id >> 3;                 // 0..63
            int kc  = (id & 7) << 2;           // 0,4,...,28
            cp_async16(&As[stage][row][kc], Ab + (size_t)row * K + k0 + kc);
            cp_async16(&Bs[stage][row][kc], Bb + (size_t)row * K + k0 + kc);
        }
    };

    const int nk = K / 32;
    load_tile(0, 0);
    asm volatile("cp.async.commit_group;\n");

    for (int kb = 0; kb < nk; kb++) {
        if (kb + 1 < nk) {
            load_tile((kb + 1) & 1, (kb + 1) * 32);
            asm volatile("cp.async.commit_group;\n");
            asm volatile("cp.async.wait_group 1;\n");
        } else {
            asm volatile("cp.async.wait_group 0;\n");
        }
        __syncthreads();

        const int st = kb & 1;
#pragma unroll
        for (int ks = 0; ks < 4; ks++) {
            const int k0 = ks * 8;
            uint32_t a[2][4];
#pragma unroll
            for (int i = 0; i < 2; i++) {
                int r = wm * 32 + i * 16 + g;
                a[i][0] = __float_as_uint(As[st][r    ][k0 + tg    ]);
                a[i][1] = __float_as_uint(As[st][r + 8][k0 + tg    ]);
                a[i][2] = __float_as_uint(As[st][r    ][k0 + tg + 4]);
                a[i][3] = __float_as_uint(As[st][r + 8][k0 + tg + 4]);
            }
            uint32_t b[4][2];
#pragma unroll
            for (int jn = 0; jn < 4; jn++) {
                int cN = wn * 32 + jn * 8 + g;
                b[jn][0] = __float_as_uint(Bs[st][cN][k0 + tg    ]);
                b[jn][1] = __float_as_uint(Bs[st][cN][k0 + tg + 4]);
            }
#pragma unroll
            for (int i = 0; i < 2; i++)
#pragma unroll
                for (int jn = 0; jn < 4; jn++)
                    mma_tf32(acc[i][jn], a[i][0], a[i][1], a[i][2], a[i][3],
                             b[jn][0], b[jn][1]);
        }
        __syncthreads();
    }

    // epilogue
#pragma unroll
    for (int jn = 0; jn < 4; jn++) {
        int col = nbase + wn * 32 + jn * 8 + tg * 2;
        float b0 = bias ? bias[col]     : 0.f;
        float b1 = bias ? bias[col + 1] : 0.f;
#pragma unroll
        for (int i = 0; i < 2; i++) {
            int row = mbase + wm * 32 + i * 16 + g;
            float v00 = fmaxf(acc[i][jn][0] + b0, 0.f);
            float v01 = fmaxf(acc[i][jn][1] + b1, 0.f);
            float v10 = fmaxf(acc[i][jn][2] + b0, 0.f);
            float v11 = fmaxf(acc[i][jn][3] + b1, 0.f);
            size_t o0 = (size_t)row * N + col;
            size_t o1 = (size_t)(row + 8) * N + col;
            out1[o0]     = rna_tf32(v00);
            out1[o0 + 1] = rna_tf32(v01);
            out1[o1]     = rna_tf32(v10);
            out1[o1 + 1] = rna_tf32(v11);
            if (out2) {
                out2[o0]     = v00;
                out2[o0 + 1] = v01;
                out2[o1]     = v10;
                out2[o1 + 1] = v11;
            }
        }
    }
}

// ---------------- LSTM gates + reward (fused, one block per batch row) ----------------
__global__ __launch_bounds__(256) void gates_kernel(
    const float* __restrict__ cc, float* __restrict__ cell,
    float* __restrict__ hs, float* __restrict__ preds,
    float* __restrict__ rewards, const float* __restrict__ rW,
    const float* __restrict__ rb, int t)
{
    const int b = blockIdx.x;
    const float* row = cc + (size_t)b * (4 * S_DIM);
    float rsum = 0.f;

    for (int s = threadIdx.x; s < S_DIM; s += 256) {
        float ci = row[s];
        float cf = row[S_DIM + s];
        float co = row[2 * S_DIM + s];
        float cg = row[3 * S_DIM + s];
        float ig = 1.f / (1.f + expf(-ci));
        float fg = 1.f / (1.f + expf(-cf));
        float og = 1.f / (1.f + expf(-co));
        float gg = tanhf(cg);
        float c_old = cell[(size_t)b * S_DIM + s];
        float cn = fg * c_old + ig * gg;
        float hn = og * tanhf(cn);
        cell[(size_t)b * S_DIM + s] = cn;
        preds[((size_t)t * B_SZ + b) * S_DIM + s] = hn;
        hs[(size_t)b * HS_DIM + s] = rna_tf32(hn);
        rsum += hn * rW[s];
    }

#pragma unroll
    for (int o = 16; o > 0; o >>= 1)
        rsum += __shfl_xor_sync(0xffffffffu, rsum, o);
    __shared__ float red[8];
    if ((threadIdx.x & 31) == 0) red[threadIdx.x >> 5] = rsum;
    __syncthreads();
    if (threadIdx.x == 0) {
        float tot = 0.f;
#pragma unroll
        for (int i = 0; i < 8; i++) tot += red[i];
        rewards[t * B_SZ + b] = tot + rb[0];
    }
}

// ---------------- small precompute kernels ----------------
__global__ void round_kernel(const float* __restrict__ src, float* __restrict__ dst, int n) {
    for (int i = blockIdx.x * blockDim.x + threadIdx.x; i < n; i += gridDim.x * blockDim.x)
        dst[i] = rna_tf32(src[i]);
}

__global__ void fc1eff_kernel(const float* __restrict__ fc1) {
    const int n = S_DIM * S_DIM;
    for (int i = blockIdx.x * blockDim.x + threadIdx.x; i < n; i += gridDim.x * blockDim.x) {
        int nr = i / S_DIM, k = i % S_DIM;
        g_fc1e[i] = rna_tf32(fc1[(size_t)nr * 2 * S_DIM + k] +
                             fc1[(size_t)nr * 2 * S_DIM + S_DIM + k]);
    }
}

__global__ void hs_init_kernel(const float* __restrict__ state, const float* __restrict__ latent) {
    const int n = B_SZ * HS_DIM;
    for (int i = blockIdx.x * blockDim.x + threadIdx.x; i < n; i += gridDim.x * blockDim.x) {
        int b = i / HS_DIM, j = i % HS_DIM;
        if (j < S_DIM)               g_hs[i] = rna_tf32(state[(size_t)b * S_DIM + j]);
        else if (j >= S_DIM + A_DIM) g_hs[i] = rna_tf32(latent[(size_t)b * P_DIM + (j - S_DIM - A_DIM)]);
        // act region filled by act_copy_kernel
    }
}

__global__ void act_copy_kernel(const float* __restrict__ act, int t) {
    int idx = blockIdx.x * blockDim.x + threadIdx.x;
    if (idx < B_SZ * A_DIM) {
        int b = idx / A_DIM, j = idx % A_DIM;
        g_hs[(size_t)b * HS_DIM + S_DIM + j] =
            rna_tf32(act[((size_t)b * T_STEPS + t) * A_DIM + j]);
    }
}

// ---------------- host orchestration ----------------
extern "C" void kernel_launch(void* const* d_in, const int* in_sizes, int n_in,
                              void* d_out, int out_size) {
    const float* state  = (const float*)d_in[0];
    const float* act    = (const float*)d_in[1];
    const float* latent = (const float*)d_in[2];
    const float* fcW    = (const float*)d_in[3];
    const float* fcb    = (const float*)d_in[4];
    const float* fc1    = (const float*)d_in[5];
    const float* fc2    = (const float*)d_in[6];
    const float* WW     = (const float*)d_in[7];
    const float* rW     = (const float*)d_in[8];
    const float* rb     = (const float*)d_in[9];

    float* out     = (float*)d_out;
    float* preds   = out;
    float* rewards = out + PRED_ELEMS;

    float *p_fcW, *p_fc1e, *p_fc2, *p_WW, *p_hs, *p_h, *p_c, *p_x1, *p_x2, *p_cc;
    cudaGetSymbolAddress((void**)&p_fcW,  g_fcW);
    cudaGetSymbolAddress((void**)&p_fc1e, g_fc1e);
    cudaGetSymbolAddress((void**)&p_fc2,  g_fc2);
    cudaGetSymbolAddress((void**)&p_WW,   g_WW);
    cudaGetSymbolAddress((void**)&p_hs,   g_hs);
    cudaGetSymbolAddress((void**)&p_h,    g_h);
    cudaGetSymbolAddress((void**)&p_c,    g_c);
    cudaGetSymbolAddress((void**)&p_x1,   g_x1);
    cudaGetSymbolAddress((void**)&p_x2,   g_x2);
    cudaGetSymbolAddress((void**)&p_cc,   g_cc);

    // precompute: round weights to tf32, fold fc1 halves, build hs0
    round_kernel<<<1024, 256>>>(fcW, p_fcW, S_DIM * HS_DIM);
    round_kernel<<<1024, 256>>>(fc2, p_fc2, S_DIM * S_DIM);
    round_kernel<<<2048, 256>>>(WW,  p_WW,  4 * S_DIM * S_DIM);
    fc1eff_kernel<<<1024, 256>>>(fc1);
    hs_init_kernel<<<512, 256>>>(state, latent);
    act_copy_kernel<<<64, 256>>>(act, 0);

    const dim3 blk(128);
    const dim3 gS(S_DIM / 64, B_SZ / 64);        // (32,4)
    const dim3 gW(4 * S_DIM / 64, B_SZ / 64);    // (128,4)

    // initial hidden & cell: relu(fc(hs0)) -> g_h (rounded) and g_c (fp32)
    gemm_tf32_kernel<<<gS, blk>>>(p_hs, p_fcW, p_h, p_c, fcb, B_SZ, S_DIM, HS_DIM);

    for (int t = 0; t < T_STEPS; t++) {
        gemm_tf32_kernel<<<gS, blk>>>(p_h,  p_fc1e, p_x1, nullptr, nullptr, B_SZ, S_DIM, S_DIM);
        gemm_tf32_kernel<<<gS, blk>>>(p_x1, p_fc2,  p_x2, nullptr, nullptr, B_SZ, S_DIM, S_DIM);
        gemm_tf32_kernel<<<gW, blk>>>(p_x2, p_WW,   p_cc, nullptr, nullptr, B_SZ, 4 * S_DIM, S_DIM);
        gates_kernel<<<B_SZ, 256>>>(p_cc, p_c, p_hs, preds, rewards, rW, rb, t);
        if (t < T_STEPS - 1) {
            act_copy_kernel<<<64, 256>>>(act, t);
            gemm_tf32_kernel<<<gS, blk>>>(p_hs, p_fcW, p_h, nullptr, fcb, B_SZ, S_DIM, HS_DIM);
        }
    }
}

// round 2
// speedup vs baseline: 2.0710x; 2.0710x over previous
#include <cuda_runtime.h>
#include <cuda_fp16.h>
#include <cstdint>
#include <math.h>

#define S_DIM 2048
#define A_DIM 64
#define P_DIM 128
#define B_SZ 256
#define T_STEPS 32
#define HS_DIM (S_DIM + A_DIM + P_DIM)   // 2240
#define PRED_ELEMS ((size_t)T_STEPS * B_SZ * S_DIM)

// ---------------- device scratch (static, no allocations) ----------------
__device__ __half g_fcW_h [S_DIM * HS_DIM];     // fc_W  fp16  [2048,2240]
__device__ __half g_fc1e_h[S_DIM * S_DIM];      // folded fc1  [2048,2048]
__device__ __half g_fc2_h [S_DIM * S_DIM];      // fc2_W fp16
__device__ __half g_WW_h  [4 * S_DIM * S_DIM];  // W_W   fp16  [8192,2048]
__device__ __half g_hs_h  [B_SZ * HS_DIM];      // [h | act_t | latent] fp16
__device__ __half g_h_h   [B_SZ * S_DIM];       // hidden carry fp16
__device__ __half g_x1_h  [B_SZ * S_DIM];
__device__ __half g_x2_h  [B_SZ * S_DIM];
__device__ float  g_c     [B_SZ * S_DIM];       // cell fp32
__device__ float  g_cc    [B_SZ * 4 * S_DIM];   // gate pre-activations fp32

// ---------------- helpers ----------------
__device__ __forceinline__ void cp_async16(void* sdst, const void* gsrc) {
    unsigned s = (unsigned)__cvta_generic_to_shared(sdst);
    asm volatile("cp.async.cg.shared.global [%0], [%1], 16;\n" :: "r"(s), "l"(gsrc));
}

__device__ __forceinline__ void ldsm_x4(uint32_t& r0, uint32_t& r1, uint32_t& r2, uint32_t& r3,
                                        const __half* p) {
    uint32_t a = (uint32_t)__cvta_generic_to_shared(p);
    asm volatile("ldmatrix.sync.aligned.m8n8.x4.shared.b16 {%0,%1,%2,%3}, [%4];\n"
                 : "=r"(r0), "=r"(r1), "=r"(r2), "=r"(r3) : "r"(a));
}

__device__ __forceinline__ void mma_f16(float c[4],
                                        uint32_t a0, uint32_t a1, uint32_t a2, uint32_t a3,
                                        uint32_t b0, uint32_t b1) {
    asm volatile(
        "mma.sync.aligned.m16n8k16.row.col.f32.f16.f16.f32 "
        "{%0,%1,%2,%3}, {%4,%5,%6,%7}, {%8,%9}, {%0,%1,%2,%3};\n"
        : "+f"(c[0]), "+f"(c[1]), "+f"(c[2]), "+f"(c[3])
        : "r"(a0), "r"(a1), "r"(a2), "r"(a3), "r"(b0), "r"(b1));
}

// ---------------- fp16 GEMM: out = relu(A @ B^T (+bias)) ----------------
// A: [M,K] fp16 row-major, B: [N,K] fp16 row-major.
// outF (fp32) and/or outH (fp16) written if non-null.
// Square CTA tile BT x BT; warps WR x WC; BK = 64 halves; double-buffered cp.async.
template<int BT, int WR, int WC>
__global__ void __launch_bounds__(WR * WC * 32) gemm_f16_kernel(
    const __half* __restrict__ A, const __half* __restrict__ Bm,
    float* __restrict__ outF, __half* __restrict__ outH,
    const float* __restrict__ bias, int M, int N, int K)
{
    constexpr int NTH = WR * WC * 32;
    constexpr int WM = BT / WR, WN = BT / WC;
    constexpr int MF = WM / 16, NF = WN / 8;
    constexpr int LDSH = 72;  // half stride per smem row (64 data + 8 pad)

    extern __shared__ __half sm[];
    __half* As = sm;                      // [2][BT][LDSH]
    __half* Bs = sm + 2 * BT * LDSH;      // [2][BT][LDSH]

    const int tid  = threadIdx.x;
    const int warp = tid >> 5;
    const int lane = tid & 31;
    const int wm = warp / WC;
    const int wn = warp % WC;
    const int g  = lane >> 2;
    const int tg = lane & 3;
    const int lr = lane & 7;
    const int lq = lane >> 3;

    const int mbase = blockIdx.y * BT;
    const int nbase = blockIdx.x * BT;
    const __half* Ab = A  + (size_t)mbase * K;
    const __half* Bb = Bm + (size_t)nbase * K;

    float acc[MF][NF][4];
#pragma unroll
    for (int i = 0; i < MF; i++)
#pragma unroll
        for (int j = 0; j < NF; j++)
#pragma unroll
            for (int e = 0; e < 4; e++) acc[i][j][e] = 0.f;

    constexpr int ITER = (BT * 8) / NTH;  // 16B chunks per thread per matrix
    auto load_tile = [&](int st, int k0) {
#pragma unroll
        for (int j = 0; j < ITER; j++) {
            int id  = tid + NTH * j;
            int row = id >> 3;
            int kc  = (id & 7) * 8;  // halves
            cp_async16(&As[(size_t)(st * BT + row) * LDSH + kc], Ab + (size_t)row * K + k0 + kc);
            cp_async16(&Bs[(size_t)(st * BT + row) * LDSH + kc], Bb + (size_t)row * K + k0 + kc);
        }
    };

    const int nk = K / 64;
    load_tile(0, 0);
    asm volatile("cp.async.commit_group;\n");

    for (int kb = 0; kb < nk; kb++) {
        if (kb + 1 < nk) {
            load_tile((kb + 1) & 1, (kb + 1) * 64);
            asm volatile("cp.async.commit_group;\n");
            asm volatile("cp.async.wait_group 1;\n");
        } else {
            asm volatile("cp.async.wait_group 0;\n");
        }
        __syncthreads();

        const int st = kb & 1;
        const __half* Abase = &As[(size_t)st * BT * LDSH];
        const __half* Bbase = &Bs[(size_t)st * BT * LDSH];

#pragma unroll
        for (int ks = 0; ks < 4; ks++) {
            const int k0 = ks * 16;
            uint32_t a[MF][4];
#pragma unroll
            for (int mf = 0; mf < MF; mf++) {
                int row = wm * WM + mf * 16 + (lq & 1) * 8 + lr;
                int col = k0 + (lq >> 1) * 8;
                ldsm_x4(a[mf][0], a[mf][1], a[mf][2], a[mf][3],
                        Abase + (size_t)row * LDSH + col);
            }
            uint32_t b[NF][2];
#pragma unroll
            for (int np = 0; np < NF / 2; np++) {
                int row = wn * WN + np * 16 + (lq >> 1) * 8 + lr;
                int col = k0 + (lq & 1) * 8;
                uint32_t r0, r1, r2, r3;
                ldsm_x4(r0, r1, r2, r3, Bbase + (size_t)row * LDSH + col);
                b[2 * np][0] = r0; b[2 * np][1] = r1;
                b[2 * np + 1][0] = r2; b[2 * np + 1][1] = r3;
            }
#pragma unroll
            for (int mf = 0; mf < MF; mf++)
#pragma unroll
                for (int nf = 0; nf < NF; nf++)
                    mma_f16(acc[mf][nf], a[mf][0], a[mf][1], a[mf][2], a[mf][3],
                            b[nf][0], b[nf][1]);
        }
        __syncthreads();
    }

    // epilogue
#pragma unroll
    for (int nf = 0; nf < NF; nf++) {
        int col = nbase + wn * WN + nf * 8 + 2 * tg;
        float b0 = bias ? bias[col]     : 0.f;
        float b1 = bias ? bias[col + 1] : 0.f;
#pragma unroll
        for (int mf = 0; mf < MF; mf++) {
            int row = mbase + wm * WM + mf * 16 + g;
            float v00 = fmaxf(acc[mf][nf][0] + b0, 0.f);
            float v01 = fmaxf(acc[mf][nf][1] + b1, 0.f);
            float v10 = fmaxf(acc[mf][nf][2] + b0, 0.f);
            float v11 = fmaxf(acc[mf][nf][3] + b1, 0.f);
            size_t o0 = (size_t)row * N + col;
            size_t o1 = (size_t)(row + 8) * N + col;
            if (outF) {
                *(float2*)(outF + o0) = make_float2(v00, v01);
                *(float2*)(outF + o1) = make_float2(v10, v11);
            }
            if (outH) {
                *(__half2*)(outH + o0) = __floats2half2_rn(v00, v01);
                *(__half2*)(outH + o1) = __floats2half2_rn(v10, v11);
            }
        }
    }
}

// ---------------- LSTM gates + reward + act staging (one block per batch row) ----------------
__global__ void __launch_bounds__(256) gates_kernel(
    const float* __restrict__ cc, float* __restrict__ cell,
    __half* __restrict__ hs, float* __restrict__ preds,
    float* __restrict__ rewards, const float* __restrict__ rW,
    const float* __restrict__ rb, const float* __restrict__ act, int t)
{
    const int b = blockIdx.x;
    const float* row = cc + (size_t)b * (4 * S_DIM);
    float rsum = 0.f;

    for (int s = threadIdx.x; s < S_DIM; s += 256) {
        float ci = row[s];
        float cf = row[S_DIM + s];
        float co = row[2 * S_DIM + s];
        float cg = row[3 * S_DIM + s];
        float ig = 1.f / (1.f + expf(-ci));
        float fg = 1.f / (1.f + expf(-cf));
        float og = 1.f / (1.f + expf(-co));
        float gg = tanhf(cg);
        float c_old = cell[(size_t)b * S_DIM + s];
        float cn = fg * c_old + ig * gg;
        float hn = og * tanhf(cn);
        cell[(size_t)b * S_DIM + s] = cn;
        preds[((size_t)t * B_SZ + b) * S_DIM + s] = hn;
        hs[(size_t)b * HS_DIM + s] = __float2half(hn);
        rsum += hn * rW[s];
    }

    // stage act[:, t, :] for the next fc GEMM
    for (int j = threadIdx.x; j < A_DIM; j += 256)
        hs[(size_t)b * HS_DIM + S_DIM + j] =
            __float2half(act[((size_t)b * T_STEPS + t) * A_DIM + j]);

#pragma unroll
    for (int o = 16; o > 0; o >>= 1)
        rsum += __shfl_xor_sync(0xffffffffu, rsum, o);
    __shared__ float red[8];
    if ((threadIdx.x & 31) == 0) red[threadIdx.x >> 5] = rsum;
    __syncthreads();
    if (threadIdx.x == 0) {
        float tot = 0.f;
#pragma unroll
        for (int i = 0; i < 8; i++) tot += red[i];
        rewards[t * B_SZ + b] = tot + rb[0];
    }
}

// ---------------- precompute kernels ----------------
__global__ void conv_h_kernel(const float* __restrict__ src, __half* __restrict__ dst, int n) {
    for (int i = blockIdx.x * blockDim.x + threadIdx.x; i < n; i += gridDim.x * blockDim.x)
        dst[i] = __float2half(src[i]);
}

__global__ void fc1fold_kernel(const float* __restrict__ fc1) {
    const int n = S_DIM * S_DIM;
    for (int i = blockIdx.x * blockDim.x + threadIdx.x; i < n; i += gridDim.x * blockDim.x) {
        int nr = i / S_DIM, k = i % S_DIM;
        g_fc1e_h[i] = __float2half(fc1[(size_t)nr * 2 * S_DIM + k] +
                                   fc1[(size_t)nr * 2 * S_DIM + S_DIM + k]);
    }
}

__global__ void hs_init_kernel(const float* __restrict__ state,
                               const float* __restrict__ act,
                               const float* __restrict__ latent) {
    const int n = B_SZ * HS_DIM;
    for (int i = blockIdx.x * blockDim.x + threadIdx.x; i < n; i += gridDim.x * blockDim.x) {
        int b = i / HS_DIM, j = i % HS_DIM;
        float v;
        if (j < S_DIM)              v = state[(size_t)b * S_DIM + j];
        else if (j < S_DIM + A_DIM) v = act[((size_t)b * T_STEPS + 0) * A_DIM + (j - S_DIM)];
        else                        v = latent[(size_t)b * P_DIM + (j - S_DIM - A_DIM)];
        g_hs_h[i] = __float2half(v);
    }
}

// ---------------- host orchestration ----------------
extern "C" void kernel_launch(void* const* d_in, const int* in_sizes, int n_in,
                              void* d_out, int out_size) {
    const float* state  = (const float*)d_in[0];
    const float* act    = (const float*)d_in[1];
    const float* latent = (const float*)d_in[2];
    const float* fcW    = (const float*)d_in[3];
    const float* fcb    = (const float*)d_in[4];
    const float* fc1    = (const float*)d_in[5];
    const float* fc2    = (const float*)d_in[6];
    const float* WW     = (const float*)d_in[7];
    const float* rW     = (const float*)d_in[8];
    const float* rb     = (const float*)d_in[9];

    float* out     = (float*)d_out;
    float* preds   = out;
    float* rewards = out + PRED_ELEMS;

    __half *p_fcW, *p_fc1e, *p_fc2, *p_WW, *p_hs, *p_h, *p_x1, *p_x2;
    float *p_c, *p_cc;
    cudaGetSymbolAddress((void**)&p_fcW,  g_fcW_h);
    cudaGetSymbolAddress((void**)&p_fc1e, g_fc1e_h);
    cudaGetSymbolAddress((void**)&p_fc2,  g_fc2_h);
    cudaGetSymbolAddress((void**)&p_WW,   g_WW_h);
    cudaGetSymbolAddress((void**)&p_hs,   g_hs_h);
    cudaGetSymbolAddress((void**)&p_h,    g_h_h);
    cudaGetSymbolAddress((void**)&p_x1,   g_x1_h);
    cudaGetSymbolAddress((void**)&p_x2,   g_x2_h);
    cudaGetSymbolAddress((void**)&p_c,    g_c);
    cudaGetSymbolAddress((void**)&p_cc,   g_cc);

    constexpr int SMEM64  = 2 * 2 * 64  * 72 * (int)sizeof(__half);  // 36864
    constexpr int SMEM128 = 2 * 2 * 128 * 72 * (int)sizeof(__half);  // 73728
    cudaFuncSetAttribute((const void*)gemm_f16_kernel<64, 2, 2>,
                         cudaFuncAttributeMaxDynamicSharedMemorySize, SMEM64);
    cudaFuncSetAttribute((const void*)gemm_f16_kernel<128, 2, 4>,
                         cudaFuncAttributeMaxDynamicSharedMemorySize, SMEM128);

    // precompute: fp32 -> fp16 weights, fold fc1 halves, build hs0
    conv_h_kernel<<<1024, 256>>>(fcW, p_fcW, S_DIM * HS_DIM);
    conv_h_kernel<<<1024, 256>>>(fc2, p_fc2, S_DIM * S_DIM);
    conv_h_kernel<<<2048, 256>>>(WW,  p_WW,  4 * S_DIM * S_DIM);
    fc1fold_kernel<<<1024, 256>>>(fc1);
    hs_init_kernel<<<512, 256>>>(state, act, latent);

    const dim3 b64(128), b128(256);
    const dim3 gS(S_DIM / 64, B_SZ / 64);            // (32,4) = 128 CTAs
    const dim3 gW(4 * S_DIM / 128, B_SZ / 128);      // (64,2) = 128 CTAs

    // initial hidden & cell: relu(fc(hs0)) -> g_h_h (fp16) and g_c (fp32)
    gemm_f16_kernel<64, 2, 2><<<gS, b64, SMEM64>>>(p_hs, p_fcW, p_c, p_h, fcb,
                                                   B_SZ, S_DIM, HS_DIM);

    for (int t = 0; t < T_STEPS; t++) {
        gemm_f16_kernel<64, 2, 2><<<gS, b64, SMEM64>>>(p_h,  p_fc1e, nullptr, p_x1, nullptr,
                                                       B_SZ, S_DIM, S_DIM);
        gemm_f16_kernel<64, 2, 2><<<gS, b64, SMEM64>>>(p_x1, p_fc2,  nullptr, p_x2, nullptr,
                                                       B_SZ, S_DIM, S_DIM);
        gemm_f16_kernel<128, 2, 4><<<gW, b128, SMEM128>>>(p_x2, p_WW, p_cc, nullptr, nullptr,
                                                          B_SZ, 4 * S_DIM, S_DIM);
        gates_kernel<<<B_SZ, 256>>>(p_cc, p_c, p_hs, preds, rewards, rW, rb, act, t);
        if (t < T_STEPS - 1)
            gemm_f16_kernel<64, 2, 2><<<gS, b64, SMEM64>>>(p_hs, p_fcW, nullptr, p_h, fcb,
                                                           B_SZ, S_DIM, HS_DIM);
    }
}

// round 4
// speedup vs baseline: 2.2080x; 1.0661x over previous
#include <cuda_runtime.h>
#include <cuda_fp16.h>
#include <cstdint>
#include <math.h>

#define S_DIM 2048
#define A_DIM 64
#define P_DIM 128
#define B_SZ 256
#define T_STEPS 32
#define HS_DIM (S_DIM + A_DIM + P_DIM)   // 2240
#define PRED_ELEMS ((size_t)T_STEPS * B_SZ * S_DIM)

// ---------------- device scratch (static, no allocations) ----------------
__device__ __half g_fcW_h [S_DIM * HS_DIM];     // fc_W fp16 [2048,2240]
__device__ __half g_fc1e_h[S_DIM * S_DIM];      // folded fc1 [2048,2048]
__device__ __half g_fc2_h [S_DIM * S_DIM];      // fc2 fp16
__device__ __half g_WWi_h [4 * S_DIM * S_DIM];  // W_W gate-interleaved [8192,2048]
__device__ __half g_hs_h  [B_SZ * HS_DIM];      // [h | act_t | latent] fp16
__device__ __half g_h_h   [B_SZ * S_DIM];       // hidden carry fp16
__device__ __half g_x1_h  [B_SZ * S_DIM];
__device__ __half g_x2_h  [B_SZ * S_DIM];
__device__ float  g_c     [B_SZ * S_DIM];       // cell fp32

// ---------------- helpers ----------------
__device__ __forceinline__ void cp16(void* sdst, const void* gsrc) {
    unsigned s = (unsigned)__cvta_generic_to_shared(sdst);
    asm volatile("cp.async.cg.shared.global [%0], [%1], 16;\n" :: "r"(s), "l"(gsrc));
}

__device__ __forceinline__ void ldsm_x4(uint32_t& r0, uint32_t& r1, uint32_t& r2, uint32_t& r3,
                                        const __half* p) {
    uint32_t a = (uint32_t)__cvta_generic_to_shared(p);
    asm volatile("ldmatrix.sync.aligned.m8n8.x4.shared.b16 {%0,%1,%2,%3}, [%4];\n"
                 : "=r"(r0), "=r"(r1), "=r"(r2), "=r"(r3) : "r"(a));
}

__device__ __forceinline__ void mma_f16(float c[4],
                                        uint32_t a0, uint32_t a1, uint32_t a2, uint32_t a3,
                                        uint32_t b0, uint32_t b1) {
    asm volatile(
        "mma.sync.aligned.m16n8k16.row.col.f32.f16.f16.f32 "
        "{%0,%1,%2,%3}, {%4,%5,%6,%7}, {%8,%9}, {%0,%1,%2,%3};\n"
        : "+f"(c[0]), "+f"(c[1]), "+f"(c[2]), "+f"(c[3])
        : "r"(a0), "r"(a1), "r"(a2), "r"(a3), "r"(b0), "r"(b1));
}

#define LDSH 72   // halves per smem row (64 data + 8 pad); 144B, 16B-aligned rows

// ================= generic fp16 HMMA GEMM: out = relu(A @ B^T (+bias)) =================
// A: [M,K] fp16 row-major, B: [N,K] fp16 row-major. 4-stage cp.async, BK=64.
// BM x BN CTA tile, WR x WC warps (warp tile (BM/WR) x (BN/WC)).
template<int BM, int BN, int WR, int WC>
__global__ void __launch_bounds__(256) gemm_hmma(
    const __half* __restrict__ A, const __half* __restrict__ Bm,
    float* __restrict__ outF, __half* __restrict__ outH,
    const float* __restrict__ bias, int N, int K)
{
    constexpr int NSTG = 4;
    constexpr int NTH  = WR * WC * 32;
    constexpr int WM = BM / WR, WN = BN / WC;
    constexpr int MF = WM / 16, NF = WN / 8;
    constexpr int ROWS = BM + BN;
    constexpr int ITER = ROWS * 8 / NTH;

    extern __shared__ __half sm[];

    const int tid  = threadIdx.x;
    const int warp = tid >> 5;
    const int lane = tid & 31;
    const int wm = warp / WC;
    const int wn = warp % WC;
    const int g  = lane >> 2;
    const int tg = lane & 3;
    const int lr = lane & 7;
    const int lq = lane >> 3;

    const int mbase = blockIdx.y * BM;
    const int nbase = blockIdx.x * BN;
    const __half* Ab = A  + (size_t)mbase * K;
    const __half* Bb = Bm + (size_t)nbase * K;
    const int nk = K >> 6;

    float acc[MF][NF][4];
#pragma unroll
    for (int i = 0; i < MF; i++)
#pragma unroll
        for (int j = 0; j < NF; j++)
#pragma unroll
            for (int e = 0; e < 4; e++) acc[i][j][e] = 0.f;

    auto load_stage = [&](int st, int kb) {
        const int k0 = kb * 64;
        __half* Ao = sm + (size_t)st * ROWS * LDSH;
        __half* Bo = Ao + (size_t)BM * LDSH;
#pragma unroll
        for (int i = 0; i < ITER; i++) {
            int id  = tid + i * NTH;
            int row = id >> 3;
            int kc  = (id & 7) * 8;
            if (row < BM)
                cp16(Ao + (size_t)row * LDSH + kc, Ab + (size_t)row * K + k0 + kc);
            else
                cp16(Bo + (size_t)(row - BM) * LDSH + kc,
                     Bb + (size_t)(row - BM) * K + k0 + kc);
        }
        asm volatile("cp.async.commit_group;\n" ::: "memory");
    };

    // prologue: fill NSTG-1 stages
    load_stage(0, 0);
    load_stage(1, 1);
    load_stage(2, 2);

    for (int kb = 0; kb < nk; kb++) {
        const int rem = nk - 1 - kb;
        if (rem >= 2)      asm volatile("cp.async.wait_group 2;\n" ::: "memory");
        else if (rem == 1) asm volatile("cp.async.wait_group 1;\n" ::: "memory");
        else               asm volatile("cp.async.wait_group 0;\n" ::: "memory");
        __syncthreads();

        if (kb + 3 < nk) load_stage((kb + 3) & 3, kb + 3);

        const int st = kb & 3;
        const __half* Abase = sm + (size_t)st * ROWS * LDSH;
        const __half* Bbase = Abase + (size_t)BM * LDSH;

#pragma unroll
        for (int ks = 0; ks < 4; ks++) {
            const int k0 = ks * 16;
            uint32_t a[MF][4];
#pragma unroll
            for (int mf = 0; mf < MF; mf++) {
                int row = wm * WM + mf * 16 + (lq & 1) * 8 + lr;
                int col = k0 + (lq >> 1) * 8;
                ldsm_x4(a[mf][0], a[mf][1], a[mf][2], a[mf][3],
                        Abase + (size_t)row * LDSH + col);
            }
            uint32_t b[NF][2];
#pragma unroll
            for (int np = 0; np < NF / 2; np++) {
                int row = wn * WN + np * 16 + (lq >> 1) * 8 + lr;
                int col = k0 + (lq & 1) * 8;
                uint32_t r0, r1, r2, r3;
                ldsm_x4(r0, r1, r2, r3, Bbase + (size_t)row * LDSH + col);
                b[2 * np][0] = r0; b[2 * np][1] = r1;
                b[2 * np + 1][0] = r2; b[2 * np + 1][1] = r3;
            }
#pragma unroll
            for (int mf = 0; mf < MF; mf++)
#pragma unroll
                for (int nf = 0; nf < NF; nf++)
                    mma_f16(acc[mf][nf], a[mf][0], a[mf][1], a[mf][2], a[mf][3],
                            b[nf][0], b[nf][1]);
        }
    }

    // epilogue
#pragma unroll
    for (int nf = 0; nf < NF; nf++) {
        int col = nbase + wn * WN + nf * 8 + 2 * tg;
        float b0 = bias ? bias[col]     : 0.f;
        float b1 = bias ? bias[col + 1] : 0.f;
#pragma unroll
        for (int mf = 0; mf < MF; mf++) {
            int row = mbase + wm * WM + mf * 16 + g;
            float v00 = fmaxf(acc[mf][nf][0] + b0, 0.f);
            float v01 = fmaxf(acc[mf][nf][1] + b1, 0.f);
            float v10 = fmaxf(acc[mf][nf][2] + b0, 0.f);
            float v11 = fmaxf(acc[mf][nf][3] + b1, 0.f);
            size_t o0 = (size_t)row * N + col;
            size_t o1 = (size_t)(row + 8) * N + col;
            if (outF) {
                *(float2*)(outF + o0) = make_float2(v00, v01);
                *(float2*)(outF + o1) = make_float2(v10, v11);
            }
            if (outH) {
                *(__half2*)(outH + o0) = __floats2half2_rn(v00, v01);
                *(__half2*)(outH + o1) = __floats2half2_rn(v10, v11);
            }
        }
    }
}

// ================= WW GEMM fused with LSTM gates / reward / act staging =================
// W_W pre-interleaved: row n = 4*s + gate. CTA tile 128x128 (32 s-values), 8 warps.
__global__ void __launch_bounds__(256) ww_gates_fused(
    const __half* __restrict__ A,       // x2 [256, 2048]
    const __half* __restrict__ Bm,      // WW interleaved [8192, 2048]
    float* __restrict__ cell,
    __half* __restrict__ hs,
    float* __restrict__ preds,
    float* __restrict__ rewards,
    const float* __restrict__ rW,
    const float* __restrict__ act, int t)
{
    constexpr int BM = 128, BN = 128, WR = 2, WC = 4;
    constexpr int NTH = 256;
    constexpr int WM = BM / WR, WN = BN / WC;   // 64, 32
    constexpr int MF = WM / 16, NF = WN / 8;    // 4, 4
    constexpr int ROWS = BM + BN;
    constexpr int ITER = ROWS * 8 / NTH;        // 8
    constexpr int K = S_DIM;
    constexpr int nk = K / 64;                  // 32
    constexpr int EST = 132;                    // fp32 epilogue stride (16B-aligned quads)

    extern __shared__ __half sm[];

    const int tid  = threadIdx.x;
    const int warp = tid >> 5;
    const int lane = tid & 31;
    const int wm = warp / WC;
    const int wn = warp % WC;
    const int g  = lane >> 2;
    const int tg = lane & 3;
    const int lr = lane & 7;
    const int lq = lane >> 3;

    const int mbase = blockIdx.y * BM;
    const int nbase = blockIdx.x * BN;
    const __half* Ab = A  + (size_t)mbase * K;
    const __half* Bb = Bm + (size_t)nbase * K;

    float acc[MF][NF][4];
#pragma unroll
    for (int i = 0; i < MF; i++)
#pragma unroll
        for (int j = 0; j < NF; j++)
#pragma unroll
            for (int e = 0; e < 4; e++) acc[i][j][e] = 0.f;

    auto load_stage = [&](int st, int kb) {
        const int k0 = kb * 64;
        __half* Ao = sm + (size_t)st * ROWS * LDSH;
        __half* Bo = Ao + (size_t)BM * LDSH;
#pragma unroll
        for (int i = 0; i < ITER; i++) {
            int id  = tid + i * NTH;
            int row = id >> 3;
            int kc  = (id & 7) * 8;
            if (row < BM)
                cp16(Ao + (size_t)row * LDSH + kc, Ab + (size_t)row * K + k0 + kc);
            else
                cp16(Bo + (size_t)(row - BM) * LDSH + kc,
                     Bb + (size_t)(row - BM) * K + k0 + kc);
        }
        asm volatile("cp.async.commit_group;\n" ::: "memory");
    };

    load_stage(0, 0);
    load_stage(1, 1);
    load_stage(2, 2);

    for (int kb = 0; kb < nk; kb++) {
        const int rem = nk - 1 - kb;
        if (rem >= 2)      asm volatile("cp.async.wait_group 2;\n" ::: "memory");
        else if (rem == 1) asm volatile("cp.async.wait_group 1;\n" ::: "memory");
        else               asm volatile("cp.async.wait_group 0;\n" ::: "memory");
        __syncthreads();

        if (kb + 3 < nk) load_stage((kb + 3) & 3, kb + 3);

        const int st = kb & 3;
        const __half* Abase = sm + (size_t)st * ROWS * LDSH;
        const __half* Bbase = Abase + (size_t)BM * LDSH;

#pragma unroll
        for (int ks = 0; ks < 4; ks++) {
            const int k0 = ks * 16;
            uint32_t a[MF][4];
#pragma unroll
            for (int mf = 0; mf < MF; mf++) {
                int row = wm * WM + mf * 16 + (lq & 1) * 8 + lr;
                int col = k0 + (lq >> 1) * 8;
                ldsm_x4(a[mf][0], a[mf][1], a[mf][2], a[mf][3],
                        Abase + (size_t)row * LDSH + col);
            }
            uint32_t b[NF][2];
#pragma unroll
            for (int np = 0; np < NF / 2; np++) {
                int row = wn * WN + np * 16 + (lq >> 1) * 8 + lr;
                int col = k0 + (lq & 1) * 8;
                uint32_t r0, r1, r2, r3;
                ldsm_x4(r0, r1, r2, r3, Bbase + (size_t)row * LDSH + col);
                b[2 * np][0] = r0; b[2 * np][1] = r1;
                b[2 * np + 1][0] = r2; b[2 * np + 1][1] = r3;
            }
#pragma unroll
            for (int mf = 0; mf < MF; mf++)
#pragma unroll
                for (int nf = 0; nf < NF; nf++)
                    mma_f16(acc[mf][nf], a[mf][0], a[mf][1], a[mf][2], a[mf][3],
                            b[nf][0], b[nf][1]);
        }
    }

    // ---- fused epilogue: exchange via smem, then gates ----
    __syncthreads();
    float* smf = (float*)sm;  // [128][EST]
#pragma unroll
    for (int nf = 0; nf < NF; nf++) {
        int col = wn * WN + nf * 8 + 2 * tg;
#pragma unroll
        for (int mf = 0; mf < MF; mf++) {
            int row = wm * WM + mf * 16 + g;
            *(float2*)&smf[(size_t)row * EST + col]       = make_float2(acc[mf][nf][0], acc[mf][nf][1]);
            *(float2*)&smf[(size_t)(row + 8) * EST + col] = make_float2(acc[mf][nf][2], acc[mf][nf][3]);
        }
    }
    __syncthreads();

    const int b_local = tid >> 1;
    const int b = mbase + b_local;
    float rsum = 0.f;
#pragma unroll
    for (int i = 0; i < 16; i++) {
        int s_local = (tid & 1) * 16 + i;
        float4 q = *(float4*)&smf[(size_t)b_local * EST + 4 * s_local];
        float ci = fmaxf(q.x, 0.f);
        float cf = fmaxf(q.y, 0.f);
        float co = fmaxf(q.z, 0.f);
        float cg = fmaxf(q.w, 0.f);
        float ig = 1.f / (1.f + expf(-ci));
        float fg = 1.f / (1.f + expf(-cf));
        float og = 1.f / (1.f + expf(-co));
        float gg = tanhf(cg);
        int s_glob = (nbase >> 2) + s_local;
        size_t cidx = (size_t)b * S_DIM + s_glob;
        float cn = fg * cell[cidx] + ig * gg;
        float hn = og * tanhf(cn);
        cell[cidx] = cn;
        preds[((size_t)t * B_SZ + b) * S_DIM + s_glob] = hn;
        hs[(size_t)b * HS_DIM + s_glob] = __float2half(hn);
        rsum += hn * rW[s_glob];
    }
    rsum += __shfl_xor_sync(0xffffffffu, rsum, 1);
    if (!(tid & 1)) atomicAdd(&rewards[t * B_SZ + b], rsum);

    // stage act[:, t, :] for next fc (only n-tile 0)
    if (nbase == 0) {
        for (int idx = tid; idx < BM * A_DIM; idx += NTH) {
            int bl = idx >> 6, a = idx & 63;
            int bb = mbase + bl;
            hs[(size_t)bb * HS_DIM + S_DIM + a] =
                __float2half(act[((size_t)bb * T_STEPS + t) * A_DIM + a]);
        }
    }
}

// ---------------- precompute kernels ----------------
__global__ void conv_h_kernel(const float* __restrict__ src, __half* __restrict__ dst, int n) {
    for (int i = blockIdx.x * blockDim.x + threadIdx.x; i < n; i += gridDim.x * blockDim.x)
        dst[i] = __float2half(src[i]);
}

__global__ void fc1fold_kernel(const float* __restrict__ fc1) {
    const int n = S_DIM * S_DIM;
    for (int i = blockIdx.x * blockDim.x + threadIdx.x; i < n; i += gridDim.x * blockDim.x) {
        int nr = i / S_DIM, k = i % S_DIM;
        g_fc1e_h[i] = __float2half(fc1[(size_t)nr * 2 * S_DIM + k] +
                                   fc1[(size_t)nr * 2 * S_DIM + S_DIM + k]);
    }
}

__global__ void ww_interleave_kernel(const float* __restrict__ WW) {
    const size_t n = (size_t)4 * S_DIM * S_DIM;
    for (size_t i = (size_t)blockIdx.x * blockDim.x + threadIdx.x; i < n;
         i += (size_t)gridDim.x * blockDim.x) {
        size_t nr = i / S_DIM, k = i % S_DIM;
        size_t s = nr >> 2, gate = nr & 3;
        g_WWi_h[i] = __float2half(WW[(gate * S_DIM + s) * S_DIM + k]);
    }
}

__global__ void hs_init_kernel(const float* __restrict__ state,
                               const float* __restrict__ act,
                               const float* __restrict__ latent) {
    const int n = B_SZ * HS_DIM;
    for (int i = blockIdx.x * blockDim.x + threadIdx.x; i < n; i += gridDim.x * blockDim.x) {
        int b = i / HS_DIM, j = i % HS_DIM;
        float v;
        if (j < S_DIM)              v = state[(size_t)b * S_DIM + j];
        else if (j < S_DIM + A_DIM) v = act[((size_t)b * T_STEPS + 0) * A_DIM + (j - S_DIM)];
        else                        v = latent[(size_t)b * P_DIM + (j - S_DIM - A_DIM)];
        g_hs_h[i] = __float2half(v);
    }
}

__global__ void rinit_kernel(float* __restrict__ rewards, const float* __restrict__ rb) {
    int i = blockIdx.x * blockDim.x + threadIdx.x;
    if (i < T_STEPS * B_SZ) rewards[i] = rb[0];
}

// ---------------- host orchestration ----------------
extern "C" void kernel_launch(void* const* d_in, const int* in_sizes, int n_in,
                              void* d_out, int out_size) {
    const float* state  = (const float*)d_in[0];
    const float* act    = (const float*)d_in[1];
    const float* latent = (const float*)d_in[2];
    const float* fcW    = (const float*)d_in[3];
    const float* fcb    = (const float*)d_in[4];
    const float* fc1    = (const float*)d_in[5];
    const float* fc2    = (const float*)d_in[6];
    const float* WW     = (const float*)d_in[7];
    const float* rW     = (const float*)d_in[8];
    const float* rb     = (const float*)d_in[9];

    float* out     = (float*)d_out;
    float* preds   = out;
    float* rewards = out + PRED_ELEMS;

    __half *p_fcW, *p_fc1e, *p_fc2, *p_WW, *p_hs, *p_h, *p_x1, *p_x2;
    float *p_c;
    cudaGetSymbolAddress((void**)&p_fcW,  g_fcW_h);
    cudaGetSymbolAddress((void**)&p_fc1e, g_fc1e_h);
    cudaGetSymbolAddress((void**)&p_fc2,  g_fc2_h);
    cudaGetSymbolAddress((void**)&p_WW,   g_WWi_h);
    cudaGetSymbolAddress((void**)&p_hs,   g_hs_h);
    cudaGetSymbolAddress((void**)&p_h,    g_h_h);
    cudaGetSymbolAddress((void**)&p_x1,   g_x1_h);
    cudaGetSymbolAddress((void**)&p_x2,   g_x2_h);
    cudaGetSymbolAddress((void**)&p_c,    g_c);

    constexpr int SMEM_S = 4 * (64 + 64)   * LDSH * (int)sizeof(__half);  //  73728
    constexpr int SMEM_W = 4 * (128 + 128) * LDSH * (int)sizeof(__half);  // 147456
    cudaFuncSetAttribute((const void*)gemm_hmma<64, 64, 2, 4>,
                         cudaFuncAttributeMaxDynamicSharedMemorySize, SMEM_S);
    cudaFuncSetAttribute((const void*)ww_gates_fused,
                         cudaFuncAttributeMaxDynamicSharedMemorySize, SMEM_W);

    // precompute
    conv_h_kernel<<<1024, 256>>>(fcW, p_fcW, S_DIM * HS_DIM);
    conv_h_kernel<<<1024, 256>>>(fc2, p_fc2, S_DIM * S_DIM);
    fc1fold_kernel<<<1024, 256>>>(fc1);
    ww_interleave_kernel<<<2048, 256>>>(WW);
    hs_init_kernel<<<512, 256>>>(state, act, latent);
    rinit_kernel<<<(T_STEPS * B_SZ + 255) / 256, 256>>>(rewards, rb);

    const dim3 blk(256);
    const dim3 gS(S_DIM / 64, B_SZ / 64);   // (32,4) = 128 CTAs
    const dim3 gW(4 * S_DIM / 128, B_SZ / 128);  // (64,2) = 128 CTAs

    // initial hidden & cell: relu(fc(hs0)) -> g_h_h (fp16) and g_c (fp32)
    gemm_hmma<64, 64, 2, 4><<<gS, blk, SMEM_S>>>(p_hs, p_fcW, p_c, p_h, fcb, S_DIM, HS_DIM);

    for (int t = 0; t < T_STEPS; t++) {
        gemm_hmma<64, 64, 2, 4><<<gS, blk, SMEM_S>>>(p_h,  p_fc1e, nullptr, p_x1, nullptr,
                                                     S_DIM, S_DIM);
        gemm_hmma<64, 64, 2, 4><<<gS, blk, SMEM_S>>>(p_x1, p_fc2,  nullptr, p_x2, nullptr,
                                                     S_DIM, S_DIM);
        ww_gates_fused<<<gW, blk, SMEM_W>>>(p_x2, p_WW, p_c, p_hs, preds, rewards, rW, act, t);
        if (t < T_STEPS - 1)
            gemm_hmma<64, 64, 2, 4><<<gS, blk, SMEM_S>>>(p_hs, p_fcW, nullptr, p_h, fcb,
                                                         S_DIM, HS_DIM);
    }
}